// round 1
// baseline (speedup 1.0000x reference)
#include <cuda_runtime.h>

// Problem shape (fixed by setup_inputs):
//   x1: [B=32, C=64, h=42, w=42]       float32
//   x2: [B=32, S=25, C=64, h=42, w=42] float32
//   out: [B, S*h*w] = [32, 44100]      float32
// out[b, s*HW + p] = sqrt( sum_c (x1[b,c,p] - x2[b,s,c,p])^2 )

#define B_  32
#define S_  25
#define C_  64
#define HW_ 1764          // 42*42
#define HW4_ 441          // HW/4 (exact)
#define TOTAL_ (B_ * S_ * HW4_)   // 352800 threads, one per 4 pixels

__global__ __launch_bounds__(256)
void euclidean_block_kernel(const float* __restrict__ x1,
                            const float* __restrict__ x2,
                            float* __restrict__ out) {
    int t = blockIdx.x * blockDim.x + threadIdx.x;
    if (t >= TOTAL_) return;

    int p4 = t % HW4_;          // which float4 within the 1764-pixel plane
    int bs = t / HW4_;          // (b*S + s)
    int b  = bs / S_;

    // Base pointers for this (b) / (b,s); all offsets are multiples of
    // HW_*4 = 7056 bytes, so float4 alignment holds.
    const float4* __restrict__ x1p =
        reinterpret_cast<const float4*>(x1 + (size_t)b * C_ * HW_) + p4;
    const float4* __restrict__ x2p =
        reinterpret_cast<const float4*>(x2 + (size_t)bs * C_ * HW_) + p4;

    float ax = 0.f, ay = 0.f, az = 0.f, aw = 0.f;

    #pragma unroll 8
    for (int c = 0; c < C_; ++c) {
        float4 a = x1p[c * HW4_];
        float4 v = x2p[c * HW4_];
        float d0 = a.x - v.x;
        float d1 = a.y - v.y;
        float d2 = a.z - v.z;
        float d3 = a.w - v.w;
        ax = fmaf(d0, d0, ax);
        ay = fmaf(d1, d1, ay);
        az = fmaf(d2, d2, az);
        aw = fmaf(d3, d3, aw);
    }

    float4 r;
    r.x = sqrtf(ax);
    r.y = sqrtf(ay);
    r.z = sqrtf(az);
    r.w = sqrtf(aw);

    // Output layout [B, S*HW] is contiguous as (b*S + s)*HW + p.
    reinterpret_cast<float4*>(out)[(size_t)bs * HW4_ + p4] = r;
}

extern "C" void kernel_launch(void* const* d_in, const int* in_sizes, int n_in,
                              void* d_out, int out_size) {
    const float* x1 = (const float*)d_in[0];
    const float* x2 = (const float*)d_in[1];
    float* out = (float*)d_out;

    const int threads = 256;
    const int blocks = (TOTAL_ + threads - 1) / threads;
    euclidean_block_kernel<<<blocks, threads>>>(x1, x2, out);
}

// round 2
// speedup vs baseline: 1.1930x; 1.1930x over previous
#include <cuda_runtime.h>

// Problem shape (fixed by setup_inputs):
//   x1: [B=32, C=64, h=42, w=42]       float32
//   x2: [B=32, S=25, C=64, h=42, w=42] float32
//   out: [B, S*h*w] = [32, 44100]      float32
// out[b, s*HW + p] = sqrt( sum_c (x1[b,c,p] - x2[b,s,c,p])^2 )

#define B_  32
#define S_  25
#define C_  64
#define HW_ 1764          // 42*42
#define HW4_ 441          // HW/4 (exact)
#define TOTAL_ (B_ * S_ * HW4_)   // 352800 threads, one per 4 pixels

__global__ __launch_bounds__(256, 3)
void euclidean_block_kernel(const float* __restrict__ x1,
                            const float* __restrict__ x2,
                            float* __restrict__ out) {
    int t = blockIdx.x * blockDim.x + threadIdx.x;
    if (t >= TOTAL_) return;

    int p4 = t % HW4_;          // which float4 within the 1764-pixel plane
    int bs = t / HW4_;          // (b*S + s)
    int b  = bs / S_;

    const float4* __restrict__ x1p =
        reinterpret_cast<const float4*>(x1 + (size_t)b * C_ * HW_) + p4;
    const float4* __restrict__ x2p =
        reinterpret_cast<const float4*>(x2 + (size_t)bs * C_ * HW_) + p4;

    float ax = 0.f, ay = 0.f, az = 0.f, aw = 0.f;

    // 8 channels per batch: 16 independent float4 loads issued back-to-back
    // before any consumption -> MLP ~16 per thread.
    #pragma unroll
    for (int cb = 0; cb < C_; cb += 8) {
        float4 a[8], v[8];
        #pragma unroll
        for (int i = 0; i < 8; ++i) {
            a[i] = x1p[(cb + i) * HW4_];
        }
        #pragma unroll
        for (int i = 0; i < 8; ++i) {
            v[i] = __ldcs(&x2p[(cb + i) * HW4_]);   // streaming: evict-first
        }
        #pragma unroll
        for (int i = 0; i < 8; ++i) {
            float d0 = a[i].x - v[i].x;
            float d1 = a[i].y - v[i].y;
            float d2 = a[i].z - v[i].z;
            float d3 = a[i].w - v[i].w;
            ax = fmaf(d0, d0, ax);
            ay = fmaf(d1, d1, ay);
            az = fmaf(d2, d2, az);
            aw = fmaf(d3, d3, aw);
        }
    }

    float4 r;
    r.x = sqrtf(ax);
    r.y = sqrtf(ay);
    r.z = sqrtf(az);
    r.w = sqrtf(aw);

    reinterpret_cast<float4*>(out)[(size_t)bs * HW4_ + p4] = r;
}

extern "C" void kernel_launch(void* const* d_in, const int* in_sizes, int n_in,
                              void* d_out, int out_size) {
    const float* x1 = (const float*)d_in[0];
    const float* x2 = (const float*)d_in[1];
    float* out = (float*)d_out;

    const int threads = 256;
    const int blocks = (TOTAL_ + threads - 1) / threads;
    euclidean_block_kernel<<<blocks, threads>>>(x1, x2, out);
}